// round 1
// baseline (speedup 1.0000x reference)
#include <cuda_runtime.h>

// Problem constants (fixed by the reference)
#define DIM   4096
#define RANK  32
#define NPREF 4
#define NSUFF 4

// ---------------------------------------------------------------------------
// Bulk copy: hidden_states -> out, float4 grid-stride. Pure HBM streaming.
// ---------------------------------------------------------------------------
__global__ __launch_bounds__(256) void copy_kernel(const float4* __restrict__ in,
                                                   float4* __restrict__ out,
                                                   long n4) {
    long i = (long)blockIdx.x * blockDim.x + threadIdx.x;
    long stride = (long)gridDim.x * blockDim.x;
    for (; i < n4; i += stride) {
        out[i] = in[i];
    }
}

// ---------------------------------------------------------------------------
// Edit kernel: one CTA per edited row (B*8 = 32 CTAs).
//   j in [0,4): prefix position  offsets[b] + j        (prefix weights)
//   j in [4,8): suffix position  offsets[b]+seqlens[b] + (j-8)  (suffix weights)
// Row edit: s = relu(x·Wsrc^T + b) - x·Wproj^T ; out_row = x + s·Wproj
// ---------------------------------------------------------------------------
__global__ __launch_bounds__(256) void edit_kernel(
    const float* __restrict__ hs,
    const float* __restrict__ Wsrc_p, const float* __restrict__ bsrc_p,
    const float* __restrict__ Wproj_p,
    const float* __restrict__ Wsrc_s, const float* __restrict__ bsrc_s,
    const float* __restrict__ Wproj_s,
    const int* __restrict__ offsets, const int* __restrict__ seqlens,
    float* __restrict__ out)
{
    __shared__ float xs[DIM];
    __shared__ float dots[2 * RANK];   // [0,32): src dots, [32,64): proj dots
    __shared__ float s[RANK];

    const int blk = blockIdx.x;
    const int b = blk >> 3;
    const int j = blk & 7;

    int pos;
    const float *Wsrc, *bsrc, *Wproj;
    if (j < NPREF) {
        pos = offsets[b] + j;
        Wsrc = Wsrc_p; bsrc = bsrc_p; Wproj = Wproj_p;
    } else {
        pos = offsets[b] + seqlens[b] + (j - 8);   // j=4..7 -> -4..-1
        Wsrc = Wsrc_s; bsrc = bsrc_s; Wproj = Wproj_s;
    }

    const int tid = threadIdx.x;
    const long row_off = ((long)b * 4096 + pos) * DIM;

    // Stage x into shared (float4)
    const float4* x4  = (const float4*)(hs + row_off);
    float4*       xs4 = (float4*)xs;
    for (int i = tid; i < DIM / 4; i += 256) xs4[i] = x4[i];
    __syncthreads();

    // 64 dot products: 8 warps, 8 dots each, warp-reduced
    const int warp = tid >> 5;
    const int lane = tid & 31;
    #pragma unroll
    for (int k = 0; k < 8; k++) {
        const int di = warp + 8 * k;   // 0..63
        const float4* W4 = (const float4*)((di < RANK)
                               ? (Wsrc  + (long)di * DIM)
                               : (Wproj + (long)(di - RANK) * DIM));
        float acc = 0.f;
        for (int i = lane; i < DIM / 4; i += 32) {
            float4 w  = W4[i];
            float4 xv = xs4[i];
            acc += w.x * xv.x + w.y * xv.y + w.z * xv.z + w.w * xv.w;
        }
        #pragma unroll
        for (int o = 16; o > 0; o >>= 1)
            acc += __shfl_xor_sync(0xffffffff, acc, o);
        if (lane == 0) dots[di] = acc;
    }
    __syncthreads();

    if (tid < RANK) {
        float v = dots[tid] + bsrc[tid];
        v = v > 0.f ? v : 0.f;
        s[tid] = v - dots[tid + RANK];
    }
    __syncthreads();

    // out_row = x + s · Wproj   (rank-32 recombination, coalesced over d)
    float4* o4 = (float4*)(out + row_off);
    for (int i = tid; i < DIM / 4; i += 256) {
        float4 acc = xs4[i];
        #pragma unroll
        for (int r = 0; r < RANK; r++) {
            float4 w = ((const float4*)(Wproj + (long)r * DIM))[i];
            float sr = s[r];
            acc.x += sr * w.x;
            acc.y += sr * w.y;
            acc.z += sr * w.z;
            acc.w += sr * w.w;
        }
        o4[i] = acc;
    }
}

extern "C" void kernel_launch(void* const* d_in, const int* in_sizes, int n_in,
                              void* d_out, int out_size) {
    const float* hs      = (const float*)d_in[0];
    const float* Wsrc_p  = (const float*)d_in[1];
    const float* bsrc_p  = (const float*)d_in[2];
    const float* Wproj_p = (const float*)d_in[3];
    const float* Wsrc_s  = (const float*)d_in[4];
    const float* bsrc_s  = (const float*)d_in[5];
    const float* Wproj_s = (const float*)d_in[6];
    const int*   offsets = (const int*)d_in[7];
    const int*   seqlens = (const int*)d_in[8];
    float* out = (float*)d_out;

    const long n4 = (long)out_size / 4;   // float4 count
    copy_kernel<<<8192, 256>>>((const float4*)hs, (float4*)out, n4);

    edit_kernel<<<4 * (NPREF + NSUFF), 256>>>(
        hs, Wsrc_p, bsrc_p, Wproj_p, Wsrc_s, bsrc_s, Wproj_s,
        offsets, seqlens, out);
}

// round 2
// speedup vs baseline: 1.2610x; 1.2610x over previous
#include <cuda_runtime.h>

#define DIM   4096
#define RANK  32
#define NROWS 32          // B(4) * 8 edited rows
#define NDOTS 64          // per row: 32 src + 32 proj

// Scratch for the 64 dot products per edited row (device global: no alloc).
__device__ float g_dots[NROWS * NDOTS];

// ---------------------------------------------------------------------------
// Kernel A: one warp per (edited row j, dot index di).
//   j = 0..31  ->  b = j>>3, slot = j&7
//   slot<4: prefix pos = off+slot (prefix weights)
//   slot>=4: suffix pos = off+seq-8+slot (suffix weights)
//   di<32: Wsrc row di ; di>=32: Wproj row di-32
// 2048 warps = 256 CTAs x 8 warps.
// ---------------------------------------------------------------------------
__global__ __launch_bounds__(256) void dots_kernel(
    const float* __restrict__ hs,
    const float* __restrict__ Wsrc_p, const float* __restrict__ Wproj_p,
    const float* __restrict__ Wsrc_s, const float* __restrict__ Wproj_s,
    const int* __restrict__ offsets, const int* __restrict__ seqlens)
{
    const int warp = threadIdx.x >> 5;
    const int lane = threadIdx.x & 31;
    const int gw = blockIdx.x * 8 + warp;     // 0..2047
    const int j  = gw >> 6;                   // edited row 0..31
    const int di = gw & 63;                   // dot 0..63

    const int b = j >> 3;
    const int slot = j & 7;
    int pos;
    const float *Wsrc, *Wproj;
    if (slot < 4) {
        pos = offsets[b] + slot;
        Wsrc = Wsrc_p; Wproj = Wproj_p;
    } else {
        pos = offsets[b] + seqlens[b] - 8 + slot;
        Wsrc = Wsrc_s; Wproj = Wproj_s;
    }

    const float4* x4 = (const float4*)(hs + ((long)b * 4096 + pos) * DIM);
    const float4* W4 = (const float4*)((di < RANK)
                           ? (Wsrc  + (long)di * DIM)
                           : (Wproj + (long)(di - RANK) * DIM));

    // 4096 floats = 1024 float4 = 32 iters/lane; unroll x8 for MLP
    float acc = 0.f;
    #pragma unroll 8
    for (int i = lane; i < DIM / 4; i += 32) {
        float4 w  = W4[i];
        float4 xv = x4[i];
        acc += w.x * xv.x + w.y * xv.y + w.z * xv.z + w.w * xv.w;
    }
    #pragma unroll
    for (int o = 16; o > 0; o >>= 1)
        acc += __shfl_xor_sync(0xffffffff, acc, o);
    if (lane == 0) g_dots[j * NDOTS + di] = acc;
}

// ---------------------------------------------------------------------------
// Kernel B: one CTA (256 threads) per row of [B*L, D].
// Non-edited: pure float4 copy. Edited: out = x + s . Wproj, with
// s = relu(src_dot + bias) - proj_dot from g_dots.
// ---------------------------------------------------------------------------
__global__ __launch_bounds__(256) void fused_kernel(
    const float* __restrict__ hs,
    const float* __restrict__ bsrc_p, const float* __restrict__ Wproj_p,
    const float* __restrict__ bsrc_s, const float* __restrict__ Wproj_s,
    const int* __restrict__ offsets, const int* __restrict__ seqlens,
    float* __restrict__ out)
{
    const int row = blockIdx.x;            // 0..16383
    const int tid = threadIdx.x;
    const long base = (long)row * DIM;
    const float4* x4 = (const float4*)(hs + base);
    float4*       o4 = (float4*)(out + base);

    const int b = row >> 12;
    const int t = row & 4095;
    const int off = offsets[b];
    const int seq = seqlens[b];

    int j = -1;
    const float* bias = bsrc_p;
    const float* Wproj = Wproj_p;
    if ((unsigned)(t - off) < 4u) {
        j = b * 8 + (t - off);
    } else if ((unsigned)(t - (off + seq - 4)) < 4u) {
        j = b * 8 + 4 + (t - (off + seq - 4));
        bias = bsrc_s; Wproj = Wproj_s;
    }

    if (j < 0) {
        // plain copy: 1024 float4 / 256 threads = 4 each
        #pragma unroll
        for (int k = 0; k < 4; k++) {
            int i = tid + k * 256;
            o4[i] = x4[i];
        }
        return;
    }

    // edited row
    __shared__ float s[RANK];
    if (tid < RANK) {
        float src  = g_dots[j * NDOTS + tid] + bias[tid];
        float proj = g_dots[j * NDOTS + RANK + tid];
        s[tid] = (src > 0.f ? src : 0.f) - proj;
    }
    __syncthreads();

    #pragma unroll
    for (int k = 0; k < 4; k++) {
        int i = tid + k * 256;
        float4 acc = x4[i];
        #pragma unroll
        for (int r = 0; r < RANK; r++) {
            float4 w = ((const float4*)(Wproj + (long)r * DIM))[i];
            float sr = s[r];
            acc.x += sr * w.x;
            acc.y += sr * w.y;
            acc.z += sr * w.z;
            acc.w += sr * w.w;
        }
        o4[i] = acc;
    }
}

extern "C" void kernel_launch(void* const* d_in, const int* in_sizes, int n_in,
                              void* d_out, int out_size) {
    const float* hs      = (const float*)d_in[0];
    const float* Wsrc_p  = (const float*)d_in[1];
    const float* bsrc_p  = (const float*)d_in[2];
    const float* Wproj_p = (const float*)d_in[3];
    const float* Wsrc_s  = (const float*)d_in[4];
    const float* bsrc_s  = (const float*)d_in[5];
    const float* Wproj_s = (const float*)d_in[6];
    const int*   offsets = (const int*)d_in[7];
    const int*   seqlens = (const int*)d_in[8];
    float* out = (float*)d_out;

    dots_kernel<<<256, 256>>>(hs, Wsrc_p, Wproj_p, Wsrc_s, Wproj_s,
                              offsets, seqlens);

    const int nrows = out_size / DIM;      // 16384
    fused_kernel<<<nrows, 256>>>(hs, bsrc_p, Wproj_p, bsrc_s, Wproj_s,
                                 offsets, seqlens, out);
}